// round 3
// baseline (speedup 1.0000x reference)
#include <cuda_runtime.h>
#include <math.h>

#define BB   256      // batch
#define TT   512      // time steps
#define IDIM 128      // input dim
#define HH   256      // hidden dim
#define CDIM 1000     // classes
#define G4   (4*HH)   // 1024 gate columns
#define NCTA 128      // persistent grid size (8 x 16)

// ---------------- scratch (static device allocations; no cudaMalloc) ----------------
__device__ float g_xp[(size_t)BB * TT * G4];   // input projection for current layer
__device__ float g_hs[(size_t)BB * TT * HH];   // layer-0 hidden sequence
__device__ float g_h[2][BB * HH];              // double-buffered hidden state
__device__ unsigned int          g_arrive;     // cumulative barrier arrivals
__device__ volatile unsigned int g_release;    // barrier release counter

// ---------------- helpers ----------------
__device__ __forceinline__ float sigmoidf_(float x) {
    return 1.0f / (1.0f + __expf(-x));
}
__device__ __forceinline__ float tanhf_(float x) {
    float ax = fabsf(x);
    float e  = __expf(-2.0f * ax);
    float r  = (1.0f - e) / (1.0f + e);
    return copysignf(r, x);
}

// packed f32x2 (Blackwell): d = a*b + d over 2 lanes
__device__ __forceinline__ void fma2_(unsigned long long& d,
                                      unsigned long long a,
                                      unsigned long long b) {
    asm("fma.rn.f32x2 %0, %1, %2, %3;" : "=l"(d) : "l"(a), "l"(b), "l"(d));
}
__device__ __forceinline__ unsigned long long bcast2_(float x) {
    unsigned long long r;
    asm("mov.b64 %0, {%1, %1};" : "=l"(r) : "f"(x));
    return r;
}
__device__ __forceinline__ float2 unpack2_(unsigned long long v) {
    float2 r;
    asm("mov.b64 {%0, %1}, %2;" : "=f"(r.x), "=f"(r.y) : "l"(v));
    return r;
}

// ---------------- input projection: g_xp[m,n] = A[m,:] . W[n,:] + b1[n] + b2[n] ----------------
#define PBM 128
#define PBN 64
#define PBK 16

__global__ __launch_bounds__(256) void proj_kernel(
    const float* __restrict__ A_ext, int use_hs,
    const float* __restrict__ W,
    const float* __restrict__ b1, const float* __restrict__ b2,
    int K)
{
    __shared__ float As[PBK][PBM];
    __shared__ float Bs[PBK][PBN];

    const float* A = use_hs ? g_hs : A_ext;
    const int N  = G4;
    const int tid = threadIdx.x;
    const int m0 = blockIdx.y * PBM;
    const int n0 = blockIdx.x * PBN;
    const int tx = tid & 15;
    const int ty = tid >> 4;

    float acc[8][4];
#pragma unroll
    for (int i = 0; i < 8; i++)
#pragma unroll
        for (int j = 0; j < 4; j++) acc[i][j] = 0.0f;

    for (int kk = 0; kk < K; kk += PBK) {
#pragma unroll
        for (int it = 0; it < 2; it++) {
            int id  = tid + it * 256;
            int row = id >> 2;
            int kq  = id & 3;
            float4 v = *(const float4*)(A + (size_t)(m0 + row) * K + kk + kq * 4);
            As[kq * 4 + 0][row] = v.x;
            As[kq * 4 + 1][row] = v.y;
            As[kq * 4 + 2][row] = v.z;
            As[kq * 4 + 3][row] = v.w;
        }
        {
            int row = tid >> 2;
            int kq  = tid & 3;
            float4 v = *(const float4*)(W + (size_t)(n0 + row) * K + kk + kq * 4);
            Bs[kq * 4 + 0][row] = v.x;
            Bs[kq * 4 + 1][row] = v.y;
            Bs[kq * 4 + 2][row] = v.z;
            Bs[kq * 4 + 3][row] = v.w;
        }
        __syncthreads();

#pragma unroll
        for (int k = 0; k < PBK; k++) {
            float4 a0 = *(const float4*)&As[k][ty * 8];
            float4 a1 = *(const float4*)&As[k][ty * 8 + 4];
            float4 bv = *(const float4*)&Bs[k][tx * 4];
            float am[8] = {a0.x, a0.y, a0.z, a0.w, a1.x, a1.y, a1.z, a1.w};
            float bn[4] = {bv.x, bv.y, bv.z, bv.w};
#pragma unroll
            for (int i = 0; i < 8; i++)
#pragma unroll
                for (int j = 0; j < 4; j++)
                    acc[i][j] += am[i] * bn[j];
        }
        __syncthreads();
    }

    float bias[4];
#pragma unroll
    for (int j = 0; j < 4; j++) {
        int n = n0 + tx * 4 + j;
        bias[j] = b1[n] + b2[n];
    }
#pragma unroll
    for (int i = 0; i < 8; i++) {
        float4 o;
        o.x = acc[i][0] + bias[0];
        o.y = acc[i][1] + bias[1];
        o.z = acc[i][2] + bias[2];
        o.w = acc[i][3] + bias[3];
        *(float4*)(g_xp + (size_t)(m0 + ty * 8 + i) * N + n0 + tx * 4) = o;
    }
}

// ---------------- persistent LSTM layer kernel ----------------
// Grid (8, 16): blockIdx.x = batch slice of 32, blockIdx.y = hidden-col slice of 16.
// 256 threads: tid = bl*8 + jg;  bl in [0,32) local batch, jg in [0,8) j-pair.
// Each thread owns (1 batch) x (2 hidden cols) x (all 4 gates); c-state in registers.
// Whh slice (4 gates x 16 j x 256 k) stays in SMEM for all 512 steps.
// SMEM layout:
//   w2f:  [4][8][258] float2  (j-pairs interleaved, padded stride 258 -> conflict-free)
//   h_s:  [32][260] float     (padded stride 260 -> conflict-free)
#define W2F_FLOATS (4 * 8 * 258 * 2)           // 16512
#define HS_FLOATS  (32 * 260)                  // 8320
#define PERSIST_SMEM_BYTES ((W2F_FLOATS + HS_FLOATS) * 4)

__global__ __launch_bounds__(256, 1) void lstm_persist_kernel(
    const float* __restrict__ Whh, int write_hs)
{
    extern __shared__ float smem[];
    float* w2f = smem;
    float* h_s = smem + W2F_FLOATS;

    const int tid = threadIdx.x;
    const int jg  = tid & 7;
    const int bl  = tid >> 3;
    const int b0  = blockIdx.x * 32;
    const int j0  = blockIdx.y * 16;
    const int b   = b0 + bl;
    const int j   = j0 + 2 * jg;

    // ---- load Whh slice into SMEM as j-pairs: w2f[g][jp][k] = (W[g*H+j0+2jp][k], W[..+1][k])
    for (int idx = tid; idx < 4096; idx += 256) {
        int row = idx >> 6;          // 0..63 local gate-row
        int kq  = idx & 63;          // k quad
        int g   = row >> 4;
        int jj  = row & 15;
        float4 v = *(const float4*)(Whh + (size_t)(g * HH + j0 + jj) * HH + kq * 4);
        int jp   = jj >> 1;
        int lane = jj & 1;
        float* dst = w2f + ((g * 8 + jp) * 258 + kq * 4) * 2 + lane;
        dst[0] = v.x; dst[2] = v.y; dst[4] = v.z; dst[6] = v.w;
    }
    __syncthreads();

    float c0 = 0.0f, c1 = 0.0f;

    for (int t = 0; t < TT; t++) {
        const float* __restrict__ hprev = g_h[t & 1];
        float* __restrict__ hnext       = g_h[(t & 1) ^ 1];

        unsigned long long accA[4], accB[4];
#pragma unroll
        for (int g = 0; g < 4; g++) { accA[g] = 0ull; accB[g] = 0ull; }

        if (t > 0) {
            // stage h slice (must bypass L1: written by other SMs last step)
            for (int i = tid; i < 2048; i += 256) {
                int row = i >> 6;
                int kq  = i & 63;
                float4 v = __ldcg((const float4*)(hprev + (size_t)(b0 + row) * HH + kq * 4));
                *(float4*)&h_s[row * 260 + kq * 4] = v;
            }
            __syncthreads();

#pragma unroll 4
            for (int k = 0; k < HH; k += 4) {
                float4 hv = *(const float4*)&h_s[bl * 260 + k];
                unsigned long long h2a = bcast2_(hv.x);
                unsigned long long h2b = bcast2_(hv.y);
                unsigned long long h2c = bcast2_(hv.z);
                unsigned long long h2d = bcast2_(hv.w);
#pragma unroll
                for (int g = 0; g < 4; g++) {
                    const ulonglong2* wp =
                        (const ulonglong2*)(w2f + ((g * 8 + jg) * 258 + k) * 2);
                    ulonglong2 wA = wp[0];   // pairs at k, k+1
                    ulonglong2 wB = wp[1];   // pairs at k+2, k+3
                    fma2_(accA[g], h2a, wA.x);
                    fma2_(accB[g], h2b, wA.y);
                    fma2_(accA[g], h2c, wB.x);
                    fma2_(accB[g], h2d, wB.y);
                }
            }
        }

        // ---- gates = acc + xp ; elementwise update (c in registers)
        float2 gate[4];
#pragma unroll
        for (int g = 0; g < 4; g++) {
            float2 a  = unpack2_(accA[g]);
            float2 bb = unpack2_(accB[g]);
            float2 xv = *(const float2*)(g_xp + ((size_t)b * TT + t) * G4 + g * HH + j);
            gate[g].x = a.x + bb.x + xv.x;
            gate[g].y = a.y + bb.y + xv.y;
        }
        float i0 = sigmoidf_(gate[0].x), i1 = sigmoidf_(gate[0].y);
        float f0 = sigmoidf_(gate[1].x), f1 = sigmoidf_(gate[1].y);
        float g0 = tanhf_   (gate[2].x), g1 = tanhf_   (gate[2].y);
        float o0 = sigmoidf_(gate[3].x), o1 = sigmoidf_(gate[3].y);
        c0 = f0 * c0 + i0 * g0;
        c1 = f1 * c1 + i1 * g1;
        float2 hv2;
        hv2.x = o0 * tanhf_(c0);
        hv2.y = o1 * tanhf_(c1);
        __stcg((float2*)(hnext + (size_t)b * HH + j), hv2);
        if (write_hs)
            *(float2*)(g_hs + ((size_t)b * TT + t) * HH + j) = hv2;

        // ---- grid barrier (cumulative counter; survives replays/launches)
        __syncthreads();
        if (tid == 0) {
            __threadfence();
            unsigned cnt    = atomicAdd(&g_arrive, 1u) + 1u;
            unsigned target = ((cnt + NCTA - 1u) / NCTA) * NCTA;
            if (cnt == target) {
                g_release = cnt;
            } else {
                while ((int)(g_release - target) < 0) __nanosleep(32);
            }
            __threadfence();
        }
        __syncthreads();
    }
}

// ---------------- final classifier ----------------
__global__ __launch_bounds__(256) void fc_kernel(
    const float* __restrict__ fcW, const float* __restrict__ fcb,
    float* __restrict__ out)
{
    __shared__ float hrow[HH];
    const int b = blockIdx.x;
    const float* __restrict__ h = g_h[0];   // final h after 512 steps lands in buffer 0
    for (int k = threadIdx.x; k < HH; k += 256) hrow[k] = h[b * HH + k];
    __syncthreads();

    for (int c = threadIdx.x; c < CDIM; c += 256) {
        const float* __restrict__ w = fcW + (size_t)c * HH;
        float s = fcb[c];
#pragma unroll
        for (int k = 0; k < HH; k += 4) {
            float4 wv = *(const float4*)(w + k);
            s += hrow[k + 0] * wv.x;
            s += hrow[k + 1] * wv.y;
            s += hrow[k + 2] * wv.z;
            s += hrow[k + 3] * wv.w;
        }
        out[(size_t)b * CDIM + c] = s;
    }
}

// ---------------- launch ----------------
extern "C" void kernel_launch(void* const* d_in, const int* in_sizes, int n_in,
                              void* d_out, int out_size)
{
    const float* x    = (const float*)d_in[0];
    const float* Wih0 = (const float*)d_in[1];
    const float* Whh0 = (const float*)d_in[2];
    const float* bih0 = (const float*)d_in[3];
    const float* bhh0 = (const float*)d_in[4];
    const float* Wih1 = (const float*)d_in[5];
    const float* Whh1 = (const float*)d_in[6];
    const float* bih1 = (const float*)d_in[7];
    const float* bhh1 = (const float*)d_in[8];
    const float* fcW  = (const float*)d_in[9];
    const float* fcb  = (const float*)d_in[10];
    float* out = (float*)d_out;

    cudaFuncSetAttribute(lstm_persist_kernel,
                         cudaFuncAttributeMaxDynamicSharedMemorySize,
                         PERSIST_SMEM_BYTES);

    const dim3 proj_grid(G4 / PBN, (BB * TT) / PBM);  // (16, 1024)
    const dim3 pers_grid(BB / 32, HH / 16);           // (8, 16) = 128 CTAs

    // ---- layer 0 ----
    proj_kernel<<<proj_grid, 256>>>(x, 0, Wih0, bih0, bhh0, IDIM);
    lstm_persist_kernel<<<pers_grid, 256, PERSIST_SMEM_BYTES>>>(Whh0, 1);

    // ---- layer 1 ----
    proj_kernel<<<proj_grid, 256>>>(nullptr, 1, Wih1, bih1, bhh1, HH);
    lstm_persist_kernel<<<pers_grid, 256, PERSIST_SMEM_BYTES>>>(Whh1, 0);

    // ---- classifier ----
    fc_kernel<<<BB, 256>>>(fcW, fcb, out);
}